// round 1
// baseline (speedup 1.0000x reference)
#include <cuda_runtime.h>
#include <math.h>

#define B_TOT 512
#define T_LEN 1024
#define DX    32
#define DZ    64
#define DY    256
#define BB    4                 // batch rows per CTA
#define NCTA  (B_TOT / BB)      // 128
#define NTHR  256
#define ALPHA 0.125f

// Packed fp32x2 FMA (Blackwell): d = a*b + c on a 64-bit register pair.
__device__ __forceinline__ float2 ffma2(float2 a, float2 b, float2 c) {
    unsigned long long au = *reinterpret_cast<unsigned long long*>(&a);
    unsigned long long bu = *reinterpret_cast<unsigned long long*>(&b);
    unsigned long long cu = *reinterpret_cast<unsigned long long*>(&c);
    unsigned long long du;
    asm("fma.rn.f32x2 %0, %1, %2, %3;" : "=l"(du) : "l"(au), "l"(bu), "l"(cu));
    return *reinterpret_cast<float2*>(&du);
}

__global__ __launch_bounds__(NTHR, 1)
void plrnn_kernel(const float* __restrict__ X,
                  const float* __restrict__ A,
                  const float* __restrict__ W1,   // (dz, dy) row-major
                  const float* __restrict__ W2,   // (dy, dz) row-major
                  const float* __restrict__ h1,
                  const float* __restrict__ h2,
                  float* __restrict__ out)        // (B, T, dx)
{
    __shared__ float4 szf[DZ];              // [z] -> zf for batches b0..b3
    __shared__ float4 sh [DY];              // [y] -> hidden for batches b0..b3
    __shared__ float  sPart[4][BB][DZ];     // [ygroup][b][z] partial sums

    const int t  = threadIdx.x;
    const int y  = t;              // GEMM1 role: one y per thread
    const int z1 = t & 63;         // GEMM2 role: z index
    const int g  = t >> 6;         // GEMM2 role: y-group (4 groups of 64)
    const int z  = t & 63;         // state/reduce role: z index
    const int b  = t >> 6;         // state/reduce role: local batch
    const int bg = blockIdx.x * BB + b;

    // ---- weights into registers (held across all 1024 steps) ----
    float w2r[DZ];                 // W2 row y:    W2[y][k], k = 0..63
#pragma unroll
    for (int k = 0; k < DZ; ++k) w2r[k] = W2[y * DZ + k];

    float w1r[DZ];                 // W1[z1][g*64 + j], j = 0..63
#pragma unroll
    for (int j = 0; j < DZ; ++j) w1r[j] = W1[z1 * DY + g * DZ + j];

    float2 h2d = make_float2(h2[y], h2[y]);
    const float Az  = A[z];
    const float h1z = h1[z];

    const float* Xb = X   + (size_t)bg * T_LEN * DX;
    float*       Ob = out + (size_t)bg * T_LEN * DX;

    // ---- initial state: z0[:dx] = X[:,0] (teacher force, alpha = 1), rest 0 ----
    float zcur = 0.0f;
    float x_next = 0.0f;
    if (z < DX) {
        float x0 = Xb[z];
        zcur   = (x0 != x0) ? 0.0f : x0;   // isnan -> keep 0
        x_next = x0;                        // X[:,0] is also step-0 forcing
    }

    for (int step = 0; step < T_LEN; ++step) {
        // ---- teacher forcing (state lives in this thread's register) ----
        float zf;
        if (z < DX) {
            float x = x_next;
            zf = (x != x) ? zcur : (ALPHA * x + (1.0f - ALPHA) * zcur);
        } else {
            zf = zcur;
        }
        reinterpret_cast<float*>(szf)[z * 4 + b] = zf;

        // prefetch next step's X slice (used ~1400 cyc later)
        if (z < DX && step + 1 < T_LEN)
            x_next = Xb[(size_t)(step + 1) * DX + z];

        __syncthreads();

        // ---- GEMM1: hidden[y][b] = relu( sum_k W2[y][k] * zf[k][b] + h2[y] ) ----
        float2 a01 = h2d, a23 = h2d;
#pragma unroll
        for (int k = 0; k < DZ; ++k) {
            float4 v  = szf[k];                       // broadcast LDS.128
            float2 wd = make_float2(w2r[k], w2r[k]);  // dup (alu pipe)
            a01 = ffma2(wd, make_float2(v.x, v.y), a01);
            a23 = ffma2(wd, make_float2(v.z, v.w), a23);
        }
        float4 hid;
        hid.x = fmaxf(a01.x, 0.0f);
        hid.y = fmaxf(a01.y, 0.0f);
        hid.z = fmaxf(a23.x, 0.0f);
        hid.w = fmaxf(a23.y, 0.0f);
        sh[y] = hid;                                   // STS.128, conflict-free

        __syncthreads();

        // ---- GEMM2: part[g][b][z1] = sum_j W1[z1][g*64+j] * hidden[g*64+j][b] ----
        float2 c01 = make_float2(0.0f, 0.0f);
        float2 c23 = make_float2(0.0f, 0.0f);
#pragma unroll
        for (int j = 0; j < DZ; ++j) {
            float4 hv = sh[g * DZ + j];               // broadcast LDS.128
            float2 wd = make_float2(w1r[j], w1r[j]);
            c01 = ffma2(wd, make_float2(hv.x, hv.y), c01);
            c23 = ffma2(wd, make_float2(hv.z, hv.w), c23);
        }
        sPart[g][0][z1] = c01.x;                       // conflict-free STS
        sPart[g][1][z1] = c01.y;
        sPart[g][2][z1] = c23.x;
        sPart[g][3][z1] = c23.y;

        __syncthreads();

        // ---- reduce 4 y-group partials, state update, stream output ----
        float s = (sPart[0][b][z] + sPart[1][b][z])
                + (sPart[2][b][z] + sPart[3][b][z]);
        float znew = fmaf(Az, zf, s + h1z);
        zcur = znew;
        if (z < DX)
            Ob[(size_t)step * DX + z] = znew;          // coalesced 128B per b
        // next iteration's szf write is ordered vs. this step's GEMM reads by
        // the two barriers above; sPart reuse is ordered by barrier #1+#2.
    }
}

extern "C" void kernel_launch(void* const* d_in, const int* in_sizes, int n_in,
                              void* d_out, int out_size)
{
    const float* X  = (const float*)d_in[0];   // (512, 1024, 32)
    const float* A  = (const float*)d_in[1];   // (64,)
    const float* W1 = (const float*)d_in[2];   // (64, 256)
    const float* W2 = (const float*)d_in[3];   // (256, 64)
    const float* h1 = (const float*)d_in[4];   // (64,)
    const float* h2 = (const float*)d_in[5];   // (256,)
    plrnn_kernel<<<NCTA, NTHR>>>(X, A, W1, W2, h1, h2, (float*)d_out);
}

// round 2
// speedup vs baseline: 1.1656x; 1.1656x over previous
#include <cuda_runtime.h>
#include <math.h>

#define T_LEN 1024
#define DX    32
#define DZ    64
#define DY    256
#define BB    4                 // batch rows per CTA
#define NCTA  128               // 512 / BB
#define NTHR  256
#define ALPHA 0.125f

// Packed fp32x2 FMA (Blackwell sm_103a): d = a*b + c elementwise on 64-bit pairs.
__device__ __forceinline__ float2 ffma2(float2 a, float2 b, float2 c) {
    unsigned long long au = *reinterpret_cast<unsigned long long*>(&a);
    unsigned long long bu = *reinterpret_cast<unsigned long long*>(&b);
    unsigned long long cu = *reinterpret_cast<unsigned long long*>(&c);
    unsigned long long du;
    asm("fma.rn.f32x2 %0, %1, %2, %3;" : "=l"(du) : "l"(au), "l"(bu), "l"(cu));
    return *reinterpret_cast<float2*>(&du);
}

__global__ __launch_bounds__(NTHR, 1)
void plrnn_kernel(const float* __restrict__ X,
                  const float* __restrict__ A,
                  const float* __restrict__ W1,   // (dz, dy) row-major
                  const float* __restrict__ W2,   // (dy, dz) row-major
                  const float* __restrict__ h1,
                  const float* __restrict__ h2,
                  float* __restrict__ out)        // (B, T, dx)
{
    __shared__ float szfB[BB][DZ];          // [b][k]   zf, batch-major
    __shared__ float shB [BB][DY];          // [b][y]   hidden, batch-major
    __shared__ float sPart[8][BB][DZ];      // [ygroup][b][z] partials

    const int t  = threadIdx.x;

    // state / reduce role
    const int z  = t & 63;
    const int b  = t >> 6;
    const int bg = blockIdx.x * BB + b;

    // GEMM1 role: 2 consecutive y, 2 consecutive batches
    const int y0 = (t & 127) * 2;           // y0, y0+1
    const int bh = t >> 7;
    const int b0 = 2 * bh, b1 = 2 * bh + 1;

    // GEMM2 role: 2 consecutive z, one 32-wide y group, all 4 batches
    const int zg0 = (t & 31) * 2;           // zg0, zg0+1
    const int g8  = t >> 5;                 // 0..7

    // ---- weights in registers, packed as (k even, k odd) pairs: no dup needed ----
    float2 w2a[32], w2b[32];                // W2 rows y0, y0+1
#pragma unroll
    for (int p = 0; p < 32; ++p) {
        w2a[p] = *reinterpret_cast<const float2*>(&W2[(size_t)y0 * DZ + 2 * p]);
        w2b[p] = *reinterpret_cast<const float2*>(&W2[(size_t)(y0 + 1) * DZ + 2 * p]);
    }
    float2 w1a[16], w1b[16];                // W1 rows zg0, zg0+1, cols [32*g8, +32)
#pragma unroll
    for (int p = 0; p < 16; ++p) {
        w1a[p] = *reinterpret_cast<const float2*>(&W1[(size_t)zg0 * DY + 32 * g8 + 2 * p]);
        w1b[p] = *reinterpret_cast<const float2*>(&W1[(size_t)(zg0 + 1) * DY + 32 * g8 + 2 * p]);
    }
    const float2 h2v = *reinterpret_cast<const float2*>(&h2[y0]);
    const float  Az  = A[z];
    const float  h1z = h1[z];

    const float* Xb = X   + (size_t)bg * T_LEN * DX;
    float*       Ob = out + (size_t)bg * T_LEN * DX;

    // ---- z0: first dx dims forced with alpha=1, rest zero ----
    float zcur = 0.0f, x_next = 0.0f;
    if (z < DX) {
        float x0 = Xb[z];
        zcur   = (x0 != x0) ? 0.0f : x0;    // NaN -> keep 0
        x_next = x0;                         // step-0 forcing reuses X[:,0]
    }

    for (int step = 0; step < T_LEN; ++step) {
        // ---- phase 0: teacher forcing, publish zf (thread owns slot [b][z]) ----
        float zf;
        if (z < DX) {
            float x = x_next;
            zf = (x != x) ? zcur : fmaf(ALPHA, x, (1.0f - ALPHA) * zcur);
        } else {
            zf = zcur;
        }
        szfB[b][z] = zf;
        if (z < DX && step + 1 < T_LEN)
            x_next = Xb[(size_t)(step + 1) * DX + z];   // prefetch, used next iter
        __syncthreads();                                // B1: zf ready

        // ---- GEMM1: hidden[y][b] = relu(W2[y,:]·zf[:,b] + h2[y]) ----
        // acc pair = (even-k sum, odd-k sum); 1 broadcast LDS.128 feeds 4 FFMA2.
        float2 a00 = {0.f, 0.f}, a01 = {0.f, 0.f};
        float2 a10 = {0.f, 0.f}, a11 = {0.f, 0.f};
        const float4* v0p = reinterpret_cast<const float4*>(szfB[b0]);
        const float4* v1p = reinterpret_cast<const float4*>(szfB[b1]);
#pragma unroll
        for (int kq = 0; kq < 16; ++kq) {
            float4 v0 = v0p[kq];
            float4 v1 = v1p[kq];
            float2 lo0 = make_float2(v0.x, v0.y), hi0 = make_float2(v0.z, v0.w);
            float2 lo1 = make_float2(v1.x, v1.y), hi1 = make_float2(v1.z, v1.w);
            a00 = ffma2(w2a[2 * kq],     lo0, a00);
            a00 = ffma2(w2a[2 * kq + 1], hi0, a00);
            a01 = ffma2(w2a[2 * kq],     lo1, a01);
            a01 = ffma2(w2a[2 * kq + 1], hi1, a01);
            a10 = ffma2(w2b[2 * kq],     lo0, a10);
            a10 = ffma2(w2b[2 * kq + 1], hi0, a10);
            a11 = ffma2(w2b[2 * kq],     lo1, a11);
            a11 = ffma2(w2b[2 * kq + 1], hi1, a11);
        }
        float2 s0, s1;
        s0.x = fmaxf(a00.x + a00.y + h2v.x, 0.0f);      // (y0, b0)
        s0.y = fmaxf(a10.x + a10.y + h2v.y, 0.0f);      // (y1, b0)
        s1.x = fmaxf(a01.x + a01.y + h2v.x, 0.0f);      // (y0, b1)
        s1.y = fmaxf(a11.x + a11.y + h2v.y, 0.0f);      // (y1, b1)
        *reinterpret_cast<float2*>(&shB[b0][y0]) = s0;  // STS.64, conflict-free
        *reinterpret_cast<float2*>(&shB[b1][y0]) = s1;
        __syncthreads();                                // B2: hidden ready

        // ---- GEMM2: part[g8][b][z] = W1[z, 32g8:32g8+32]·hidden[32g8:,b] ----
        float2 c0[BB], c1[BB];
#pragma unroll
        for (int bb = 0; bb < BB; ++bb) { c0[bb] = make_float2(0.f, 0.f);
                                          c1[bb] = make_float2(0.f, 0.f); }
#pragma unroll
        for (int yq = 0; yq < 8; ++yq) {
#pragma unroll
            for (int bb = 0; bb < BB; ++bb) {
                float4 hv = *reinterpret_cast<const float4*>(&shB[bb][32 * g8 + 4 * yq]);
                float2 lo = make_float2(hv.x, hv.y), hi = make_float2(hv.z, hv.w);
                c0[bb] = ffma2(w1a[2 * yq],     lo, c0[bb]);
                c0[bb] = ffma2(w1a[2 * yq + 1], hi, c0[bb]);
                c1[bb] = ffma2(w1b[2 * yq],     lo, c1[bb]);
                c1[bb] = ffma2(w1b[2 * yq + 1], hi, c1[bb]);
            }
        }
#pragma unroll
        for (int bb = 0; bb < BB; ++bb) {
            float2 pr;
            pr.x = c0[bb].x + c0[bb].y;                 // z = zg0
            pr.y = c1[bb].x + c1[bb].y;                 // z = zg0+1
            *reinterpret_cast<float2*>(&sPart[g8][bb][zg0]) = pr;  // STS.64
        }
        __syncthreads();                                // B3: partials ready

        // ---- reduce 8 groups + state update + output (no barrier needed:
        //      ordering vs next step's writes is provided by B1/B2 of step+1) ----
        float s = 0.0f;
#pragma unroll
        for (int g = 0; g < 8; ++g) s += sPart[g][b][z];
        float znew = fmaf(Az, zf, s + h1z);
        zcur = znew;
        if (z < DX)
            Ob[(size_t)step * DX + z] = znew;           // coalesced 128B/warp
    }
}

extern "C" void kernel_launch(void* const* d_in, const int* in_sizes, int n_in,
                              void* d_out, int out_size)
{
    const float* X  = (const float*)d_in[0];   // (512, 1024, 32)
    const float* A  = (const float*)d_in[1];   // (64,)
    const float* W1 = (const float*)d_in[2];   // (64, 256)
    const float* W2 = (const float*)d_in[3];   // (256, 64)
    const float* h1 = (const float*)d_in[4];   // (64,)
    const float* h2 = (const float*)d_in[5];   // (256,)
    plrnn_kernel<<<NCTA, NTHR>>>(X, A, W1, W2, h1, h2, (float*)d_out);
}

// round 3
// speedup vs baseline: 1.2251x; 1.0510x over previous
#include <cuda_runtime.h>
#include <math.h>

#define T_LEN 1024
#define DX    32
#define DZ    64
#define DY    256
#define BB    4
#define NCTA  128
#define NTHR  256
#define ALPHA 0.125f
#define KHPAD 36                 // padded offset of the second k-half in szfB rows

// Packed fp32x2 FMA (Blackwell sm_103a): d = a*b + c elementwise on 64-bit pairs.
__device__ __forceinline__ float2 ffma2(float2 a, float2 b, float2 c) {
    unsigned long long au = *reinterpret_cast<unsigned long long*>(&a);
    unsigned long long bu = *reinterpret_cast<unsigned long long*>(&b);
    unsigned long long cu = *reinterpret_cast<unsigned long long*>(&c);
    unsigned long long du;
    asm("fma.rn.f32x2 %0, %1, %2, %3;" : "=l"(du) : "l"(au), "l"(bu), "l"(cu));
    return *reinterpret_cast<float2*>(&du);
}

__global__ __launch_bounds__(NTHR, 1)
void plrnn_kernel(const float* __restrict__ X,
                  const float* __restrict__ A,
                  const float* __restrict__ W1,   // (dz, dy) row-major
                  const float* __restrict__ W2,   // (dy, dz) row-major
                  const float* __restrict__ h1,
                  const float* __restrict__ h2,
                  float* __restrict__ out)        // (B, T, dx)
{
    __shared__ float szfB[BB][2 * KHPAD];   // [b][k-half * 36 + k%32], padded halves
    __shared__ float shB [BB][DY];          // [b][y] hidden
    __shared__ float sPart[8][BB][DZ];      // [ygroup][b][z] partials

    const int t  = threadIdx.x;

    // state / reduce role
    const int z   = t & 63;
    const int b   = t >> 6;
    const int bg  = blockIdx.x * BB + b;
    const int zsl = (z >> 5) * KHPAD + (z & 31);   // padded szfB slot for this z

    // GEMM1 role: 2 consecutive y, one k-half, all 4 batches; partner = lane^1
    const int q   = t >> 1;                  // 0..127
    const int y0  = 2 * q;
    const int kh  = t & 1;                   // k-half (0: k<32, 1: k>=32)
    const int kb  = kh * KHPAD;              // padded base in szfB row

    // GEMM2 role: 2 consecutive z, one 32-wide y group, all 4 batches
    const int zg0 = (t & 31) * 2;
    const int g8  = t >> 5;

    // ---- weights in registers, natural (even,odd) float2 pairs (no dup) ----
    float2 w2a[16], w2b[16];                 // W2 rows y0/y0+1, this thread's k-half
#pragma unroll
    for (int p = 0; p < 16; ++p) {
        w2a[p] = *reinterpret_cast<const float2*>(&W2[(size_t)y0 * DZ + 32 * kh + 2 * p]);
        w2b[p] = *reinterpret_cast<const float2*>(&W2[(size_t)(y0 + 1) * DZ + 32 * kh + 2 * p]);
    }
    float2 w1a[16], w1b[16];                 // W1 rows zg0/zg0+1, cols [32*g8, +32)
#pragma unroll
    for (int p = 0; p < 16; ++p) {
        w1a[p] = *reinterpret_cast<const float2*>(&W1[(size_t)zg0 * DY + 32 * g8 + 2 * p]);
        w1b[p] = *reinterpret_cast<const float2*>(&W1[(size_t)(zg0 + 1) * DY + 32 * g8 + 2 * p]);
    }
    const float2 h2v = *reinterpret_cast<const float2*>(&h2[y0]);
    const float  Az  = A[z];
    const float  h1z = h1[z];

    const float* Xb = X   + (size_t)bg * T_LEN * DX;
    float*       Ob = out + (size_t)bg * T_LEN * DX;

    // ---- z0: first dx dims forced with alpha=1, rest zero ----
    float zcur = 0.0f, x_next = 0.0f;
    if (z < DX) {
        float x0 = Xb[z];
        zcur   = (x0 != x0) ? 0.0f : x0;     // NaN -> keep 0
        x_next = x0;                          // step-0 forcing reuses X[:,0]
    }

    for (int step = 0; step < T_LEN; ++step) {
        // ---- phase 0: teacher forcing, publish zf ----
        float zf;
        if (z < DX) {
            float x = x_next;
            zf = (x != x) ? zcur : fmaf(ALPHA, x, (1.0f - ALPHA) * zcur);
        } else {
            zf = zcur;
        }
        szfB[b][zsl] = zf;
        if (z < DX && step + 1 < T_LEN)
            x_next = Xb[(size_t)(step + 1) * DX + z];   // prefetch for next iter
        __syncthreads();                                 // B1: zf ready

        // ---- GEMM1 (k-split): partial[y0/y1][bb] over this thread's 32 k ----
        float2 a0[BB], a1[BB];
#pragma unroll
        for (int bb = 0; bb < BB; ++bb) { a0[bb] = make_float2(0.f, 0.f);
                                          a1[bb] = make_float2(0.f, 0.f); }
#pragma unroll
        for (int j = 0; j < 8; ++j) {
#pragma unroll
            for (int bb = 0; bb < BB; ++bb) {
                float4 v = *reinterpret_cast<const float4*>(&szfB[bb][kb + 4 * j]);
                float2 lo = make_float2(v.x, v.y), hi = make_float2(v.z, v.w);
                a0[bb] = ffma2(w2a[2 * j],     lo, a0[bb]);
                a0[bb] = ffma2(w2a[2 * j + 1], hi, a0[bb]);
                a1[bb] = ffma2(w2b[2 * j],     lo, a1[bb]);
                a1[bb] = ffma2(w2b[2 * j + 1], hi, a1[bb]);
            }
        }
        // combine k-halves with partner lane (lane^1), relu, store 2 batches each
        {
            float s0[BB], s1[BB];
#pragma unroll
            for (int bb = 0; bb < BB; ++bb) {
                s0[bb] = a0[bb].x + a0[bb].y;
                s1[bb] = a1[bb].x + a1[bb].y;
                s0[bb] += __shfl_xor_sync(0xffffffffu, s0[bb], 1);
                s1[bb] += __shfl_xor_sync(0xffffffffu, s1[bb], 1);
            }
            // kh==0 stores batches 0,1; kh==1 stores batches 2,3
            int bs = kh * 2;
#pragma unroll
            for (int u = 0; u < 2; ++u) {
                int bb = bs + u;
                float2 hv;
                hv.x = fmaxf(s0[bb] + h2v.x, 0.0f);
                hv.y = fmaxf(s1[bb] + h2v.y, 0.0f);
                *reinterpret_cast<float2*>(&shB[bb][y0]) = hv;
            }
        }
        __syncthreads();                                 // B2: hidden ready

        // ---- GEMM2: part[g8][b][z] = W1[z, 32g8:+32] . hidden[32g8:+32, b] ----
        float2 c0[BB], c1[BB];
#pragma unroll
        for (int bb = 0; bb < BB; ++bb) { c0[bb] = make_float2(0.f, 0.f);
                                          c1[bb] = make_float2(0.f, 0.f); }
#pragma unroll
        for (int yq = 0; yq < 8; ++yq) {
#pragma unroll
            for (int bb = 0; bb < BB; ++bb) {
                float4 hv = *reinterpret_cast<const float4*>(&shB[bb][32 * g8 + 4 * yq]);
                float2 lo = make_float2(hv.x, hv.y), hi = make_float2(hv.z, hv.w);
                c0[bb] = ffma2(w1a[2 * yq],     lo, c0[bb]);
                c0[bb] = ffma2(w1a[2 * yq + 1], hi, c0[bb]);
                c1[bb] = ffma2(w1b[2 * yq],     lo, c1[bb]);
                c1[bb] = ffma2(w1b[2 * yq + 1], hi, c1[bb]);
            }
        }
#pragma unroll
        for (int bb = 0; bb < BB; ++bb) {
            float2 pr;
            pr.x = c0[bb].x + c0[bb].y;                  // z = zg0
            pr.y = c1[bb].x + c1[bb].y;                  // z = zg0+1
            *reinterpret_cast<float2*>(&sPart[g8][bb][zg0]) = pr;
        }
        __syncthreads();                                 // B3: partials ready

        // ---- reduce 8 groups + state update + output ----
        float s = 0.0f;
#pragma unroll
        for (int g = 0; g < 8; ++g) s += sPart[g][b][z];
        float znew = fmaf(Az, zf, s + h1z);
        zcur = znew;
        if (z < DX)
            Ob[(size_t)step * DX + z] = znew;            // coalesced
    }
}

extern "C" void kernel_launch(void* const* d_in, const int* in_sizes, int n_in,
                              void* d_out, int out_size)
{
    const float* X  = (const float*)d_in[0];   // (512, 1024, 32)
    const float* A  = (const float*)d_in[1];   // (64,)
    const float* W1 = (const float*)d_in[2];   // (64, 256)
    const float* W2 = (const float*)d_in[3];   // (256, 64)
    const float* h1 = (const float*)d_in[4];   // (64,)
    const float* h2 = (const float*)d_in[5];   // (256,)
    plrnn_kernel<<<NCTA, NTHR>>>(X, A, W1, W2, h1, h2, (float*)d_out);
}